// round 15
// baseline (speedup 1.0000x reference)
#include <cuda_runtime.h>
#include <cuda_bf16.h>
#include <cstdint>

// Problem constants
#define B_IMG 4096
#define V_TXT 5
#define D_DIM 512
#define N_TXT (B_IMG * V_TXT)         // 20480
#define SCALE_F 14.285714285714286f   // 1/0.07
#define MSHIFT_F 14.285714285714286f

// Arch-specific feature detection (tcgen05 requires an sm_103a/f device pass)
#if defined(__CUDA_ARCH_FEAT_SM103_ALL) || defined(__CUDA_ARCH_SPECIFIC__) || defined(__CUDA_ARCH_FAMILY_SPECIFIC__)
#define HAS_TCGEN05 1
#else
#define HAS_TCGEN05 0
#endif

// ---------------- device scratch ----------------
__device__ __nv_bfloat16 g_imgb[(size_t)B_IMG * D_DIM];
__device__ __nv_bfloat16 g_txtb[(size_t)N_TXT * D_DIM];
__device__ float g_rowsum[B_IMG];
__device__ float g_colsum[N_TXT];
__device__ float g_possum;            // RAW (unscaled) positive-logit sum
__device__ float g_logsum;
__device__ unsigned int g_count;

// ---------------- convert + init (fused), 16B vectorized stores --------------
__global__ void convert_kernel(const float* __restrict__ img,
                               const float* __restrict__ txt) {
    const int gid = blockIdx.x * blockDim.x + threadIdx.x;
    if (gid < B_IMG) g_rowsum[gid] = 0.0f;
    if (gid < N_TXT) g_colsum[gid] = 0.0f;
    if (gid == 0) { g_possum = 0.0f; g_logsum = 0.0f; g_count = 0u; }

    const int IMG8 = B_IMG * D_DIM / 8;
    const int TOT8 = IMG8 + N_TXT * D_DIM / 8;
    for (int i = gid; i < TOT8; i += gridDim.x * blockDim.x) {
        const float4* src; uint4* dst;
        if (i < IMG8) {
            src = reinterpret_cast<const float4*>(img) + 2 * (size_t)i;
            dst = reinterpret_cast<uint4*>(g_imgb) + i;
        } else {
            int j = i - IMG8;
            src = reinterpret_cast<const float4*>(txt) + 2 * (size_t)j;
            dst = reinterpret_cast<uint4*>(g_txtb) + j;
        }
        float4 v0 = src[0], v1 = src[1];
        union { __nv_bfloat162 h[4]; uint4 u; } o;
        o.h[0] = __floats2bfloat162_rn(v0.x, v0.y);
        o.h[1] = __floats2bfloat162_rn(v0.z, v0.w);
        o.h[2] = __floats2bfloat162_rn(v1.x, v1.y);
        o.h[3] = __floats2bfloat162_rn(v1.z, v1.w);
        *dst = o.u;
    }
}

// ===== PATH A: persistent tcgen05 cg2, A-resident smem, N=256, dbl-buffer D ==
// 74 clusters x 2 CTAs, 288 threads (warps 0-7 load+epilogue, tid256 issuer).
// Contiguous band-major tile ranges: A (128 rows x 512 K = 128KB/CTA) loaded
// once per band into persistent smem; B streamed via 4-stage 16KB ring.
// Tile N=256 -> D double buffer in TMEM (cols [0,256) / [256,512)); epilogue
// of tile t overlaps MMA of tile t+1. EPI(b) gates buffer reuse (tile t-2).
#define NCLUSTERS 74
#define NTILE_C   80                   // 20480 / 256
#define NTILES    1280                 // 16 bands x 80 col-tiles
#define TC_BK 64
#define NSTAGE 4

#define SM_TMEMPTR 0u
#define SM_AFULL   8u                            // cnt=256 (A cp.async)
#define SM_ABOTH   16u                           // cnt=2 (issuer relay, on rank0)
#define SM_FLOCAL(s) (24u + 8u*(uint32_t)(s))    // cnt=256 (B cp.async)
#define SM_FULL(s)   (56u + 8u*(uint32_t)(s))    // cnt=2 (issuer of each CTA)
#define SM_DONE(s)   (88u + 8u*(uint32_t)(s))    // cnt=1 (multicast commit)
#define SM_EPI(b)    (120u + 8u*(uint32_t)(b))   // cnt=2 (tid0 of each CTA)
#define SM_A       1024u                          // 8 x 16KB = 128KB persistent
#define SM_B       133120u                        // 4 x 16KB ring
#define SM_TOTAL   198656u

// idesc cg2: f32 accum, bf16 A/B, N=256 per dispatch, M=256
#define MMA_IDESC_CG2 ((1u<<4)|(1u<<7)|(1u<<10)|((256u/8u)<<17)|((256u/16u)<<24))
#define SWZ(x) ((x) ^ (((x) >> 3) & 0x70))

__device__ __forceinline__ uint32_t smem_u32(const void* p) {
    return (uint32_t)__cvta_generic_to_shared(p);
}
__device__ __forceinline__ void cp16(uint32_t saddr, const void* g) {
    asm volatile("cp.async.cg.shared.global [%0], [%1], 16;\n" ::"r"(saddr), "l"(g));
}
__device__ __forceinline__ void mbar_init(uint32_t a, uint32_t cnt) {
    asm volatile("mbarrier.init.shared.b64 [%0], %1;" ::"r"(a), "r"(cnt) : "memory");
}
__device__ __forceinline__ void mbar_wait(uint32_t a, uint32_t parity) {
    uint32_t done;
    asm volatile(
        "{\n\t.reg .pred p;\n\t"
        "mbarrier.try_wait.parity.acquire.cta.shared::cta.b64 p, [%1], %2;\n\t"
        "selp.b32 %0, 1, 0, p;\n\t}"
        : "=r"(done) : "r"(a), "r"(parity) : "memory");
    if (!done) {
        asm volatile(
            "{\n\t.reg .pred P1;\n\t"
            "W_%=:\n\t"
            "mbarrier.try_wait.parity.acquire.cta.shared::cta.b64 P1, [%0], %1, 0x989680;\n\t"
            "@P1 bra.uni D_%=;\n\t"
            "bra.uni W_%=;\n\t"
            "D_%=:\n\t}"
            :: "r"(a), "r"(parity) : "memory");
    }
}
__device__ __forceinline__ void mbar_wait_cluster(uint32_t a, uint32_t parity) {
    asm volatile(
        "{\n\t.reg .pred P1;\n\t"
        "W_%=:\n\t"
        "mbarrier.try_wait.parity.acquire.cluster.shared::cta.b64 P1, [%0], %1, 0x989680;\n\t"
        "@P1 bra.uni D_%=;\n\t"
        "bra.uni W_%=;\n\t"
        "D_%=:\n\t}"
        :: "r"(a), "r"(parity) : "memory");
}
__device__ __forceinline__ void mbar_arrive_rank0(uint32_t local_addr) {
    asm volatile(
        "{\n\t.reg .b32 r;\n\t"
        "mapa.shared::cluster.u32 r, %0, 0;\n\t"
        "mbarrier.arrive.shared::cluster.b64 _, [r];\n\t}"
        :: "r"(local_addr) : "memory");
}

#if HAS_TCGEN05
__device__ __forceinline__ uint64_t make_desc_sw128(uint32_t addr) {
    const uint64_t base = (uint64_t(2) << 61) | (uint64_t(1) << 46) |
                          (uint64_t(64) << 32) | (uint64_t(1) << 16);
    return base | ((uint64_t)(addr >> 4) & 0x3FFF);
}
__device__ __forceinline__ void mma_f16_ss_cg2(uint32_t d, uint64_t ad, uint64_t bd,
                                               uint32_t idesc, uint32_t en) {
    asm volatile(
        "{\n\t.reg .pred p;\n\t"
        "setp.ne.u32 p, %4, 0;\n\t"
        "tcgen05.mma.cta_group::2.kind::f16 [%0], %1, %2, %3, "
        "{%5,%5,%5,%5,%5,%5,%5,%5}, p;\n\t}"
        :: "r"(d), "l"(ad), "l"(bd), "r"(idesc), "r"(en), "r"(0u) : "memory");
}
__device__ __forceinline__ void commit_mc(uint32_t addr) {
    asm volatile(
        "tcgen05.commit.cta_group::2.mbarrier::arrive::one"
        ".shared::cluster.multicast::cluster.b64 [%0], %1;"
        ::"r"(addr), "h"((uint16_t)0x3) : "memory");
}
// Full A band (this CTA's 128 rows x 512 K) into persistent smem; arrive AFULL.
__device__ __forceinline__ void load_A_band(uint32_t sb, int band, int rank, int tid) {
    const int rowBase = band * 256 + rank * 128;
#pragma unroll
    for (int i = 0; i < 32; i++) {          // 8192 x16B total
        int idx = tid + i * 256;
        int c = idx >> 10;                  // chunk 0..7
        int rr = (idx & 1023) >> 3, seg = idx & 7;
        cp16(sb + SM_A + (uint32_t)c * 16384u + SWZ((uint32_t)(rr * 128 + seg * 16)),
             g_imgb + (size_t)(rowBase + rr) * D_DIM + c * TC_BK + seg * 8);
    }
    asm volatile("cp.async.mbarrier.arrive.noinc.shared::cta.b64 [%0];"
                 ::"r"(sb + SM_AFULL) : "memory");
}
// B chunk (this CTA's 128 local N-rows, K chunk c) into ring stage s; arrive FLOCAL.
__device__ __forceinline__ void load_B(uint32_t sb, int s, int tt, int c,
                                       int rank, int tid) {
    const int colBase = (tt % NTILE_C) * 256;
    const uint32_t stg = sb + SM_B + (uint32_t)s * 16384u;
#pragma unroll
    for (int i = 0; i < 4; i++) {           // 1024 x16B
        int idx = tid + i * 256;
        int lr = idx >> 3, seg = idx & 7;
        int grow = colBase + rank * 128 + lr;
        cp16(stg + SWZ((uint32_t)(lr * 128 + seg * 16)),
             g_txtb + (size_t)grow * D_DIM + c * TC_BK + seg * 8);
    }
    asm volatile("cp.async.mbarrier.arrive.noinc.shared::cta.b64 [%0];"
                 ::"r"(sb + SM_FLOCAL(s)) : "memory");
}
#endif  // HAS_TCGEN05

__global__ void __launch_bounds__(288, 1) __cluster_dims__(2, 1, 1)
gemm_tc_kernel() {
#if HAS_TCGEN05
    extern __shared__ char smem[];
    const uint32_t sb = smem_u32(smem);
    const int tid = threadIdx.x;
    const int w = tid >> 5, lane = tid & 31;
    uint32_t rank;
    asm("mov.u32 %0, %%cluster_ctarank;" : "=r"(rank));
    const int cid = blockIdx.x >> 1;
    const int tstart = (cid * NTILES) / NCLUSTERS;
    const int tend   = ((cid + 1) * NTILES) / NCLUSTERS;

    if (w == 0) {
        asm volatile("tcgen05.alloc.cta_group::2.sync.aligned.shared::cta.b32 [%0], %1;"
                     ::"r"(sb + SM_TMEMPTR), "r"(512u) : "memory");
        asm volatile("tcgen05.relinquish_alloc_permit.cta_group::2.sync.aligned;");
    }
    if (tid == 0) {
        mbar_init(sb + SM_AFULL, 256);
        mbar_init(sb + SM_ABOTH, 2);
#pragma unroll
        for (int s = 0; s < NSTAGE; s++) {
            mbar_init(sb + SM_FLOCAL(s), 256);
            mbar_init(sb + SM_FULL(s), 2);
            mbar_init(sb + SM_DONE(s), 1);
        }
        mbar_init(sb + SM_EPI(0), 2);
        mbar_init(sb + SM_EPI(1), 2);
    }
    __syncthreads();
    asm volatile("barrier.cluster.arrive.aligned;" ::: "memory");
    asm volatile("barrier.cluster.wait.aligned;" ::: "memory");

    uint32_t tmem;
    asm volatile("ld.shared.b32 %0, [%1];" : "=r"(tmem) : "r"(sb + SM_TMEMPTR));

    if (tid < 256) {
        // ------------- load warps 0-7 + per-tile epilogue -------------------
        int prevband = tstart / NTILE_C;
        load_A_band(sb, prevband, (int)rank, tid);     // A for first band
        load_B(sb, 0, tstart, 0, (int)rank, tid);      // chunk 0 of first tile

        int kl = 0, it = 0;
#pragma unroll 1
        for (int tt = tstart; tt < tend; tt++, it++) {
            const int rowBase = (tt / NTILE_C) * 256 + (int)rank * 128;
            const int colBase = (tt % NTILE_C) * 256;
            const int b = it & 1;

#pragma unroll 1
            for (int c = 0; c < 8; c++, kl++) {
                // stage (kl+1)%4 previous occupant = chunk kl-3; wait its MMA
                if (kl >= 3)
                    mbar_wait(sb + SM_DONE((kl - 3) % NSTAGE),
                              (uint32_t)((kl - 3) / NSTAGE) & 1u);
                if (c < 7)
                    load_B(sb, (kl + 1) % NSTAGE, tt, c + 1, (int)rank, tid);
                else if (tt + 1 < tend)
                    load_B(sb, (kl + 1) % NSTAGE, tt + 1, 0, (int)rank, tid);
            }

            // ---- epilogue: wait this tile's last chunk MMA (chunk kl-1) ----
            mbar_wait(sb + SM_DONE((kl - 1) % NSTAGE),
                      (uint32_t)((kl - 1) / NSTAGE) & 1u);
            asm volatile("tcgen05.fence::after_thread_sync;" ::: "memory");

            const int half = w >> 2, sp = w & 3;
            const int row = rowBase + sp * 32 + lane;
            float rowacc = 0.0f, pos = 0.0f;
            const int pstart = row * V_TXT - colBase - half * 128;

#pragma unroll 1
            for (int ch = 0; ch < 4; ch++) {
                uint32_t r[32];
                uint32_t taddr = tmem + b * 256 + half * 128 + ch * 32;
                asm volatile(
                    "tcgen05.ld.sync.aligned.32x32b.x32.b32 "
                    "{%0,%1,%2,%3,%4,%5,%6,%7,%8,%9,%10,%11,%12,%13,%14,%15,"
                    "%16,%17,%18,%19,%20,%21,%22,%23,%24,%25,%26,%27,%28,%29,%30,%31}, [%32];"
                    : "=r"(r[0]), "=r"(r[1]), "=r"(r[2]), "=r"(r[3]), "=r"(r[4]),
                      "=r"(r[5]), "=r"(r[6]), "=r"(r[7]), "=r"(r[8]), "=r"(r[9]),
                      "=r"(r[10]), "=r"(r[11]), "=r"(r[12]), "=r"(r[13]), "=r"(r[14]),
                      "=r"(r[15]), "=r"(r[16]), "=r"(r[17]), "=r"(r[18]), "=r"(r[19]),
                      "=r"(r[20]), "=r"(r[21]), "=r"(r[22]), "=r"(r[23]), "=r"(r[24]),
                      "=r"(r[25]), "=r"(r[26]), "=r"(r[27]), "=r"(r[28]), "=r"(r[29]),
                      "=r"(r[30]), "=r"(r[31])
                    : "r"(taddr));
                asm volatile("tcgen05.wait::ld.sync.aligned;" ::: "memory");

                float v[32];
#pragma unroll
                for (int cc = 0; cc < 32; cc++) {
                    float a = __uint_as_float(r[cc]);
                    int lc = ch * 32 + cc;
                    if (lc >= pstart && lc < pstart + V_TXT) pos += a;
                    float e = __expf(fmaf(a, SCALE_F, -MSHIFT_F));
                    v[cc] = e;
                    rowacc += e;
                }
#pragma unroll
                for (int off = 16; off >= 1; off >>= 1) {
#pragma unroll
                    for (int cc = 0; cc < 16; cc++) {
                        if (cc < off) {
                            float sent = (lane & off) ? v[cc] : v[cc + off];
                            float rcv = __shfl_xor_sync(0xffffffffu, sent, off);
                            float keep = (lane & off) ? v[cc + off] : v[cc];
                            v[cc] = keep + rcv;
                        }
                    }
                }
                atomicAdd(&g_colsum[colBase + half * 128 + ch * 32 + lane], v[0]);
            }
            atomicAdd(&g_rowsum[row], rowacc);
            if (pos != 0.0f) atomicAdd(&g_possum, pos);

            asm volatile("tcgen05.fence::before_thread_sync;" ::: "memory");
            asm volatile("bar.sync 1, 256;" ::: "memory");   // warps 0-7 only
            if (tid == 0) mbar_arrive_rank0(sb + SM_EPI(b)); // cnt=2

            // A reload if the next tile starts a new band (all MMAs reading the
            // old A completed: we just waited this tile's last DONE above).
            if (tt + 1 < tend) {
                int nb = (tt + 1) / NTILE_C;
                if (nb != prevband) {
                    prevband = nb;
                    load_A_band(sb, nb, (int)rank, tid);
                }
            }
        }
    } else if (tid == 256) {
        // ------------- issuer: ABOTH/FULL relays + MMA + DONE ---------------
        int prevband = -1, acnt = 0;
        int it = 0;
#pragma unroll 1
        for (int tt = tstart; tt < tend; tt++, it++) {
            const int band = tt / NTILE_C;
            if (band != prevband) {
                prevband = band;
                mbar_wait(sb + SM_AFULL, (uint32_t)acnt & 1u);  // local A resident
                asm volatile("fence.proxy.async.shared::cta;" ::: "memory");
                mbar_arrive_rank0(sb + SM_ABOTH);
                if (rank == 0)
                    mbar_wait_cluster(sb + SM_ABOTH, (uint32_t)acnt & 1u);
                acnt++;
            }
            const int b = it & 1, k = it >> 1;
#pragma unroll 1
            for (int c = 0; c < 8; c++) {
                const int j = it * 8 + c;
                const int s = j % NSTAGE;
                const uint32_t ph = (uint32_t)(j / NSTAGE) & 1u;
                mbar_wait(sb + SM_FLOCAL(s), ph);   // local B chunk landed
                asm volatile("fence.proxy.async.shared::cta;" ::: "memory");
                mbar_arrive_rank0(sb + SM_FULL(s));
                if (rank == 0) {
                    mbar_wait_cluster(sb + SM_FULL(s), ph);
                    if (c == 0 && k >= 1)           // buffer b's prev user: tile it-2
                        mbar_wait_cluster(sb + SM_EPI(b), (uint32_t)(k - 1) & 1u);
                    const uint64_t ad = make_desc_sw128(sb + SM_A + (uint32_t)c * 16384u);
                    const uint64_t bd = make_desc_sw128(sb + SM_B + (uint32_t)s * 16384u);
#pragma unroll
                    for (int kk = 0; kk < 4; kk++)
                        mma_f16_ss_cg2(tmem + b * 256, ad + kk * 2, bd + kk * 2,
                                       MMA_IDESC_CG2, (uint32_t)((c > 0) || (kk > 0)));
                    commit_mc(sb + SM_DONE(s));
                }
            }
        }
    }
    // (threads 257-287 fall through)

    __syncthreads();   // all 288
    if (w == 0) {
        asm volatile("tcgen05.dealloc.cta_group::2.sync.aligned.b32 %0, %1;"
                     ::"r"(tmem), "r"(512u));
    }
    asm volatile("barrier.cluster.arrive.aligned;" ::: "memory");
    asm volatile("barrier.cluster.wait.aligned;" ::: "memory");
#endif  // HAS_TCGEN05
}

// ================= PATH B: HMMA mma.sync fallback (plain sm_103) =============
__device__ __forceinline__ void mma16816(float* c, const uint32_t* a, const uint32_t* b) {
    asm volatile(
        "mma.sync.aligned.m16n8k16.row.col.f32.bf16.bf16.f32 "
        "{%0,%1,%2,%3}, {%4,%5,%6,%7}, {%8,%9}, {%0,%1,%2,%3};\n"
        : "+f"(c[0]), "+f"(c[1]), "+f"(c[2]), "+f"(c[3])
        : "r"(a[0]), "r"(a[1]), "r"(a[2]), "r"(a[3]), "r"(b[0]), "r"(b[1]));
}
__device__ __forceinline__ void cpa16(void* smem_dst, const void* gsrc) {
    uint32_t s = (uint32_t)__cvta_generic_to_shared(smem_dst);
    asm volatile("cp.async.ca.shared.global [%0], [%1], 16;\n" ::"r"(s), "l"(gsrc));
}
#define LDH 24
#define STAGE_H (128 * LDH)

__global__ void __launch_bounds__(256, 2) gemm_hmma_kernel() {
#if !HAS_TCGEN05
    __shared__ __nv_bfloat16 As[2 * STAGE_H];
    __shared__ __nv_bfloat16 Bs[2 * STAGE_H];

    const int tid = threadIdx.x;
    const int lane = tid & 31;
    const int warp = tid >> 5;
    const int g = lane >> 2;
    const int t = lane & 3;
    const int warpM = warp >> 2;
    const int warpN = warp & 3;
    const int rowBase = blockIdx.y * 128;
    const int colBase = blockIdx.x * 128;

    const int ldRow = tid >> 1;
    const int ldHalf = (tid & 1) * 8;
    const __nv_bfloat16* gA = g_imgb + (size_t)(rowBase + ldRow) * D_DIM + ldHalf;
    const __nv_bfloat16* gB = g_txtb + (size_t)(colBase + ldRow) * D_DIM + ldHalf;
    __nv_bfloat16* sA = &As[ldRow * LDH + ldHalf];
    __nv_bfloat16* sB = &Bs[ldRow * LDH + ldHalf];

    float acc[4][4][4];
#pragma unroll
    for (int mi = 0; mi < 4; mi++)
#pragma unroll
        for (int ni = 0; ni < 4; ni++)
#pragma unroll
            for (int r = 0; r < 4; r++) acc[mi][ni][r] = 0.0f;

    cpa16(sA, gA);
    cpa16(sB, gB);
    asm volatile("cp.async.commit_group;\n" ::: "memory");

    const int NSTEP = D_DIM / 16;
#pragma unroll 1
    for (int kc = 0; kc < NSTEP; kc++) {
        if (kc + 1 < NSTEP) {
            int st = (kc + 1) & 1;
            int k0 = (kc + 1) * 16;
            cpa16(sA + st * STAGE_H, gA + k0);
            cpa16(sB + st * STAGE_H, gB + k0);
            asm volatile("cp.async.commit_group;\n" ::: "memory");
            asm volatile("cp.async.wait_group 1;\n" ::: "memory");
        } else {
            asm volatile("cp.async.wait_group 0;\n" ::: "memory");
        }
        __syncthreads();

        const int buf = kc & 1;
        const uint32_t* A32 = reinterpret_cast<const uint32_t*>(As + buf * STAGE_H);
        const uint32_t* B32 = reinterpret_cast<const uint32_t*>(Bs + buf * STAGE_H);

        uint32_t a[4][4], b[4][2];
#pragma unroll
        for (int mi = 0; mi < 4; mi++) {
            int r0 = warpM * 64 + mi * 16 + g;
            a[mi][0] = A32[r0 * (LDH / 2) + t];
            a[mi][1] = A32[(r0 + 8) * (LDH / 2) + t];
            a[mi][2] = A32[r0 * (LDH / 2) + t + 4];
            a[mi][3] = A32[(r0 + 8) * (LDH / 2) + t + 4];
        }
#pragma unroll
        for (int ni = 0; ni < 4; ni++) {
            int c0 = warpN * 32 + ni * 8 + g;
            b[ni][0] = B32[c0 * (LDH / 2) + t];
            b[ni][1] = B32[c0 * (LDH / 2) + t + 4];
        }
#pragma unroll
        for (int mi = 0; mi < 4; mi++)
#pragma unroll
            for (int ni = 0; ni < 4; ni++) mma16816(acc[mi][ni], a[mi], b[ni]);

        __syncthreads();
    }

    float rp[4][2], cp[4][2];
#pragma unroll
    for (int i = 0; i < 4; i++) { rp[i][0] = rp[i][1] = cp[i][0] = cp[i][1] = 0.0f; }
    float pos = 0.0f;

#pragma unroll
    for (int mi = 0; mi < 4; mi++) {
        const int r0 = rowBase + warpM * 64 + mi * 16 + g;
        const int r1 = r0 + 8;
#pragma unroll
        for (int ni = 0; ni < 4; ni++) {
            const int c0 = colBase + warpN * 32 + ni * 8 + 2 * t;
            const int c1 = c0 + 1;
            float e00 = __expf(fmaf(acc[mi][ni][0], SCALE_F, -MSHIFT_F));
            float e01 = __expf(fmaf(acc[mi][ni][1], SCALE_F, -MSHIFT_F));
            float e10 = __expf(fmaf(acc[mi][ni][2], SCALE_F, -MSHIFT_F));
            float e11 = __expf(fmaf(acc[mi][ni][3], SCALE_F, -MSHIFT_F));
            rp[mi][0] += e00 + e01;
            rp[mi][1] += e10 + e11;
            cp[ni][0] += e00 + e10;
            cp[ni][1] += e01 + e11;
            int p0 = r0 * V_TXT;
            int p1 = r1 * V_TXT;
            if (c0 >= p0 && c0 < p0 + V_TXT) pos += acc[mi][ni][0];
            if (c1 >= p0 && c1 < p0 + V_TXT) pos += acc[mi][ni][1];
            if (c0 >= p1 && c0 < p1 + V_TXT) pos += acc[mi][ni][2];
            if (c1 >= p1 && c1 < p1 + V_TXT) pos += acc[mi][ni][3];
        }
    }

#pragma unroll
    for (int mi = 0; mi < 4; mi++)
#pragma unroll
        for (int rr = 0; rr < 2; rr++) {
            float v = rp[mi][rr];
            v += __shfl_xor_sync(0xffffffffu, v, 1);
            v += __shfl_xor_sync(0xffffffffu, v, 2);
            if (t == 0)
                atomicAdd(&g_rowsum[rowBase + warpM * 64 + mi * 16 + g + rr * 8], v);
        }
#pragma unroll
    for (int ni = 0; ni < 4; ni++)
#pragma unroll
        for (int cc = 0; cc < 2; cc++) {
            float v = cp[ni][cc];
            v += __shfl_xor_sync(0xffffffffu, v, 4);
            v += __shfl_xor_sync(0xffffffffu, v, 8);
            v += __shfl_xor_sync(0xffffffffu, v, 16);
            if (g == 0)
                atomicAdd(&g_colsum[colBase + warpN * 32 + ni * 8 + 2 * t + cc], v);
        }
    if (pos != 0.0f) atomicAdd(&g_possum, pos);
#endif  // !HAS_TCGEN05
}

// ---------------- parallel log reduction + fused writer ----------------
#define RED_BLOCKS 128
__global__ void reduce_kernel(float* out, int out_size) {
    float s = 0.0f;
    for (int i = blockIdx.x * blockDim.x + threadIdx.x; i < B_IMG;
         i += gridDim.x * blockDim.x)
        s += logf(g_rowsum[i]) * (1.0f / B_IMG);
    for (int j = blockIdx.x * blockDim.x + threadIdx.x; j < N_TXT;
         j += gridDim.x * blockDim.x)
        s += logf(g_colsum[j]) * (1.0f / N_TXT);
#pragma unroll
    for (int off = 16; off >= 1; off >>= 1) s += __shfl_xor_sync(0xffffffffu, s, off);
    __shared__ float sh[8];
    int w = threadIdx.x >> 5, lane = threadIdx.x & 31;
    if (lane == 0) sh[w] = s;
    __syncthreads();
    if (threadIdx.x == 0) {
        float b = 0.0f;
        for (int k = 0; k < 8; k++) b += sh[k];
        atomicAdd(&g_logsum, b);
        __threadfence();
        unsigned int done = atomicAdd(&g_count, 1u);
        if (done == RED_BLOCKS - 1) {
            float loss = 0.5f * (g_logsum + 2.0f * MSHIFT_F)
                         - SCALE_F * g_possum / (float)N_TXT;
            for (int k = 0; k < out_size; k++) out[k] = loss;
        }
    }
}

// ---------------- launch ----------------
extern "C" void kernel_launch(void* const* d_in, const int* in_sizes, int n_in,
                              void* d_out, int out_size) {
    const float* img = (const float*)d_in[0];
    const float* txt = (const float*)d_in[1];
    (void)in_sizes; (void)n_in;

    static int use_tc = -1;
    if (use_tc < 0) {
        cudaFuncAttributes a{};
        cudaFuncGetAttributes(&a, gemm_tc_kernel);
        use_tc = (a.numRegs > 40) ? 1 : 0;
        if (use_tc)
            cudaFuncSetAttribute(gemm_tc_kernel,
                                 cudaFuncAttributeMaxDynamicSharedMemorySize, SM_TOTAL);
    }

    convert_kernel<<<2048, 256>>>(img, txt);
    if (use_tc) {
        gemm_tc_kernel<<<2 * NCLUSTERS, 288, SM_TOTAL>>>();   // 148 CTAs, persistent
    } else {
        dim3 grid_hm(N_TXT / 128, B_IMG / 128);
        gemm_hmma_kernel<<<grid_hm, 256>>>();
    }
    reduce_kernel<<<RED_BLOCKS, 256>>>((float*)d_out, out_size);
}

// round 16
// speedup vs baseline: 1.2014x; 1.2014x over previous
#include <cuda_runtime.h>
#include <cuda_bf16.h>
#include <cstdint>

// Problem constants
#define B_IMG 4096
#define V_TXT 5
#define D_DIM 512
#define N_TXT (B_IMG * V_TXT)         // 20480
#define SCALE_F 14.285714285714286f   // 1/0.07
#define MSHIFT_F 14.285714285714286f

// Arch-specific feature detection (tcgen05 requires an sm_103a/f device pass)
#if defined(__CUDA_ARCH_FEAT_SM103_ALL) || defined(__CUDA_ARCH_SPECIFIC__) || defined(__CUDA_ARCH_FAMILY_SPECIFIC__)
#define HAS_TCGEN05 1
#else
#define HAS_TCGEN05 0
#endif

// ---------------- device scratch ----------------
__device__ __nv_bfloat16 g_imgb[(size_t)B_IMG * D_DIM];
__device__ __nv_bfloat16 g_txtb[(size_t)N_TXT * D_DIM];
__device__ float g_rowsum[B_IMG];
__device__ float g_colsum[N_TXT];
__device__ float g_possum;            // RAW (unscaled) positive-logit sum
__device__ float g_logsum;
__device__ unsigned int g_count;

// ---------------- convert + init (fused), 16B vectorized stores --------------
__global__ void convert_kernel(const float* __restrict__ img,
                               const float* __restrict__ txt) {
    const int gid = blockIdx.x * blockDim.x + threadIdx.x;
    if (gid < B_IMG) g_rowsum[gid] = 0.0f;
    if (gid < N_TXT) g_colsum[gid] = 0.0f;
    if (gid == 0) { g_possum = 0.0f; g_logsum = 0.0f; g_count = 0u; }

    const int IMG8 = B_IMG * D_DIM / 8;
    const int TOT8 = IMG8 + N_TXT * D_DIM / 8;
    for (int i = gid; i < TOT8; i += gridDim.x * blockDim.x) {
        const float4* src; uint4* dst;
        if (i < IMG8) {
            src = reinterpret_cast<const float4*>(img) + 2 * (size_t)i;
            dst = reinterpret_cast<uint4*>(g_imgb) + i;
        } else {
            int j = i - IMG8;
            src = reinterpret_cast<const float4*>(txt) + 2 * (size_t)j;
            dst = reinterpret_cast<uint4*>(g_txtb) + j;
        }
        float4 v0 = src[0], v1 = src[1];
        union { __nv_bfloat162 h[4]; uint4 u; } o;
        o.h[0] = __floats2bfloat162_rn(v0.x, v0.y);
        o.h[1] = __floats2bfloat162_rn(v0.z, v0.w);
        o.h[2] = __floats2bfloat162_rn(v1.x, v1.y);
        o.h[3] = __floats2bfloat162_rn(v1.z, v1.w);
        *dst = o.u;
    }
}

// ===== PATH A: persistent tcgen05 cg2 (R14 cadence) + A-resident smem ========
// 74 clusters x 2 CTAs, 288 threads: warps 0-7 load + epilogue, tid256 = MMA
// issuer. N=512 tiles, contiguous band-major ranges. A (128 rows x 512 K =
// 128KB/CTA) loaded once per band (AFULL/ABOTH handshake); B streamed via
// 3-stage 32KB ring (guard DONE(kl-2), R8-proven). Rest identical to R14.
#define NCLUSTERS 74
#define NTILE_C   40
#define NTILES    640                  // 16 bands x 40 col-tiles
#define TC_BK 64
#define NSTAGE 3

#define SM_TMEMPTR 0u
#define SM_AFULL   8u                            // cnt=256 (A cp.async)
#define SM_ABOTH   16u                           // cnt=2 (issuer relay, on rank0)
#define SM_FLOCAL(s) (24u + 8u*(uint32_t)(s))    // cnt=256 (B cp.async)
#define SM_FULL(s)   (48u + 8u*(uint32_t)(s))    // cnt=2 (issuer of each CTA)
#define SM_DONE(s)   (72u + 8u*(uint32_t)(s))    // cnt=1 (multicast commit)
#define SM_EPI       96u                          // cnt=2 (tid0 of each CTA)
#define SM_A       1024u                          // 8 x 16KB = 128KB persistent
#define SM_B       132096u                        // 3 x 32KB ring
#define SM_TOTAL   230400u

// idesc cg2: f32 accum, bf16 A/B, N=256 per dispatch, M=256
#define MMA_IDESC_CG2 ((1u<<4)|(1u<<7)|(1u<<10)|((256u/8u)<<17)|((256u/16u)<<24))
#define SWZ(x) ((x) ^ (((x) >> 3) & 0x70))

__device__ __forceinline__ uint32_t smem_u32(const void* p) {
    return (uint32_t)__cvta_generic_to_shared(p);
}
__device__ __forceinline__ void cp16(uint32_t saddr, const void* g) {
    asm volatile("cp.async.cg.shared.global [%0], [%1], 16;\n" ::"r"(saddr), "l"(g));
}
__device__ __forceinline__ void mbar_init(uint32_t a, uint32_t cnt) {
    asm volatile("mbarrier.init.shared.b64 [%0], %1;" ::"r"(a), "r"(cnt) : "memory");
}
__device__ __forceinline__ void mbar_wait(uint32_t a, uint32_t parity) {
    uint32_t done;
    asm volatile(
        "{\n\t.reg .pred p;\n\t"
        "mbarrier.try_wait.parity.acquire.cta.shared::cta.b64 p, [%1], %2;\n\t"
        "selp.b32 %0, 1, 0, p;\n\t}"
        : "=r"(done) : "r"(a), "r"(parity) : "memory");
    if (!done) {
        asm volatile(
            "{\n\t.reg .pred P1;\n\t"
            "W_%=:\n\t"
            "mbarrier.try_wait.parity.acquire.cta.shared::cta.b64 P1, [%0], %1, 0x989680;\n\t"
            "@P1 bra.uni D_%=;\n\t"
            "bra.uni W_%=;\n\t"
            "D_%=:\n\t}"
            :: "r"(a), "r"(parity) : "memory");
    }
}
__device__ __forceinline__ void mbar_wait_cluster(uint32_t a, uint32_t parity) {
    asm volatile(
        "{\n\t.reg .pred P1;\n\t"
        "W_%=:\n\t"
        "mbarrier.try_wait.parity.acquire.cluster.shared::cta.b64 P1, [%0], %1, 0x989680;\n\t"
        "@P1 bra.uni D_%=;\n\t"
        "bra.uni W_%=;\n\t"
        "D_%=:\n\t}"
        :: "r"(a), "r"(parity) : "memory");
}
__device__ __forceinline__ void mbar_arrive_rank0(uint32_t local_addr) {
    asm volatile(
        "{\n\t.reg .b32 r;\n\t"
        "mapa.shared::cluster.u32 r, %0, 0;\n\t"
        "mbarrier.arrive.shared::cluster.b64 _, [r];\n\t}"
        :: "r"(local_addr) : "memory");
}

#if HAS_TCGEN05
__device__ __forceinline__ uint64_t make_desc_sw128(uint32_t addr) {
    const uint64_t base = (uint64_t(2) << 61) | (uint64_t(1) << 46) |
                          (uint64_t(64) << 32) | (uint64_t(1) << 16);
    return base | ((uint64_t)(addr >> 4) & 0x3FFF);
}
__device__ __forceinline__ void mma_f16_ss_cg2(uint32_t d, uint64_t ad, uint64_t bd,
                                               uint32_t idesc, uint32_t en) {
    asm volatile(
        "{\n\t.reg .pred p;\n\t"
        "setp.ne.u32 p, %4, 0;\n\t"
        "tcgen05.mma.cta_group::2.kind::f16 [%0], %1, %2, %3, "
        "{%5,%5,%5,%5,%5,%5,%5,%5}, p;\n\t}"
        :: "r"(d), "l"(ad), "l"(bd), "r"(idesc), "r"(en), "r"(0u) : "memory");
}
__device__ __forceinline__ void commit_mc(uint32_t addr) {
    asm volatile(
        "tcgen05.commit.cta_group::2.mbarrier::arrive::one"
        ".shared::cluster.multicast::cluster.b64 [%0], %1;"
        ::"r"(addr), "h"((uint16_t)0x3) : "memory");
}
// Full A band (this CTA's 128 rows x 512 K) into persistent smem; arrive AFULL.
__device__ __forceinline__ void load_A_band(uint32_t sb, int band, int rank, int tid) {
    const int rowBase = band * 256 + rank * 128;
#pragma unroll
    for (int i = 0; i < 32; i++) {          // 8192 x16B total
        int idx = tid + i * 256;
        int c = idx >> 10;                  // chunk 0..7
        int rr = (idx & 1023) >> 3, seg = idx & 7;
        cp16(sb + SM_A + (uint32_t)c * 16384u + SWZ((uint32_t)(rr * 128 + seg * 16)),
             g_imgb + (size_t)(rowBase + rr) * D_DIM + c * TC_BK + seg * 8);
    }
    asm volatile("cp.async.mbarrier.arrive.noinc.shared::cta.b64 [%0];"
                 ::"r"(sb + SM_AFULL) : "memory");
}
// B chunk (this CTA's 256 local rows of the 512-col tile, K chunk c) into
// ring stage s; arrive FLOCAL.
__device__ __forceinline__ void load_B(uint32_t sb, int s, int tt, int c,
                                       int rank, int tid) {
    const int colBase = (tt % NTILE_C) * 512;
    const uint32_t stg = sb + SM_B + (uint32_t)s * 32768u;
#pragma unroll
    for (int i = 0; i < 8; i++) {           // 2048 x16B
        int idx = tid + i * 256;
        int lr = idx >> 3, seg = idx & 7;
        int grow = colBase + ((lr >> 7) << 8) + rank * 128 + (lr & 127);
        cp16(stg + SWZ((uint32_t)(lr * 128 + seg * 16)),
             g_txtb + (size_t)grow * D_DIM + c * TC_BK + seg * 8);
    }
    asm volatile("cp.async.mbarrier.arrive.noinc.shared::cta.b64 [%0];"
                 ::"r"(sb + SM_FLOCAL(s)) : "memory");
}
#endif  // HAS_TCGEN05

__global__ void __launch_bounds__(288, 1) __cluster_dims__(2, 1, 1)
gemm_tc_kernel() {
#if HAS_TCGEN05
    extern __shared__ char smem[];
    const uint32_t sb = smem_u32(smem);
    const int tid = threadIdx.x;
    const int w = tid >> 5, lane = tid & 31;
    uint32_t rank;
    asm("mov.u32 %0, %%cluster_ctarank;" : "=r"(rank));
    const int cid = blockIdx.x >> 1;
    const int tstart = (cid * NTILES) / NCLUSTERS;
    const int tend   = ((cid + 1) * NTILES) / NCLUSTERS;

    if (w == 0) {
        asm volatile("tcgen05.alloc.cta_group::2.sync.aligned.shared::cta.b32 [%0], %1;"
                     ::"r"(sb + SM_TMEMPTR), "r"(512u) : "memory");
        asm volatile("tcgen05.relinquish_alloc_permit.cta_group::2.sync.aligned;");
    }
    if (tid == 0) {
        mbar_init(sb + SM_AFULL, 256);
        mbar_init(sb + SM_ABOTH, 2);
#pragma unroll
        for (int s = 0; s < NSTAGE; s++) {
            mbar_init(sb + SM_FLOCAL(s), 256);
            mbar_init(sb + SM_FULL(s), 2);
            mbar_init(sb + SM_DONE(s), 1);
        }
        mbar_init(sb + SM_EPI, 2);
    }
    __syncthreads();
    asm volatile("barrier.cluster.arrive.aligned;" ::: "memory");
    asm volatile("barrier.cluster.wait.aligned;" ::: "memory");

    uint32_t tmem;
    asm volatile("ld.shared.b32 %0, [%1];" : "=r"(tmem) : "r"(sb + SM_TMEMPTR));

    if (tid < 256) {
        // ------------- load warps 0-7 + per-tile epilogue -------------------
        int prevband = tstart / NTILE_C;
        load_A_band(sb, prevband, (int)rank, tid);
        load_B(sb, 0, tstart, 0, (int)rank, tid);

        int kl = 0;
#pragma unroll 1
        for (int tt = tstart; tt < tend; tt++) {
            const int rowBase = (tt / NTILE_C) * 256 + (int)rank * 128;
            const int colBase = (tt % NTILE_C) * 512;

#pragma unroll 1
            for (int c = 0; c < 8; c++, kl++) {
                // stage (kl+1)%3 previous occupant = chunk kl-2; wait its MMA
                if (kl >= 2)
                    mbar_wait(sb + SM_DONE((kl - 2) % NSTAGE),
                              (uint32_t)((kl - 2) / NSTAGE) & 1u);
                if (c < 7)
                    load_B(sb, (kl + 1) % NSTAGE, tt, c + 1, (int)rank, tid);
                else if (tt + 1 < tend)
                    load_B(sb, (kl + 1) % NSTAGE, tt + 1, 0, (int)rank, tid);
            }

            // ---- epilogue: wait this tile's last chunk MMA (chunk kl-1) ----
            mbar_wait(sb + SM_DONE((kl - 1) % NSTAGE),
                      (uint32_t)((kl - 1) / NSTAGE) & 1u);
            asm volatile("tcgen05.fence::after_thread_sync;" ::: "memory");

            const int half = w >> 2, sp = w & 3;
            const int row = rowBase + sp * 32 + lane;
            float rowacc = 0.0f, pos = 0.0f;
            const int pstart = row * V_TXT - colBase - half * 256;

#pragma unroll 1
            for (int ch = 0; ch < 8; ch++) {
                uint32_t r[32];
                uint32_t taddr = tmem + half * 256 + ch * 32;
                asm volatile(
                    "tcgen05.ld.sync.aligned.32x32b.x32.b32 "
                    "{%0,%1,%2,%3,%4,%5,%6,%7,%8,%9,%10,%11,%12,%13,%14,%15,"
                    "%16,%17,%18,%19,%20,%21,%22,%23,%24,%25,%26,%27,%28,%29,%30,%31}, [%32];"
                    : "=r"(r[0]), "=r"(r[1]), "=r"(r[2]), "=r"(r[3]), "=r"(r[4]),
                      "=r"(r[5]), "=r"(r[6]), "=r"(r[7]), "=r"(r[8]), "=r"(r[9]),
                      "=r"(r[10]), "=r"(r[11]), "=r"(r[12]), "=r"(r[13]), "=r"(r[14]),
                      "=r"(r[15]), "=r"(r[16]), "=r"(r[17]), "=r"(r[18]), "=r"(r[19]),
                      "=r"(r[20]), "=r"(r[21]), "=r"(r[22]), "=r"(r[23]), "=r"(r[24]),
                      "=r"(r[25]), "=r"(r[26]), "=r"(r[27]), "=r"(r[28]), "=r"(r[29]),
                      "=r"(r[30]), "=r"(r[31])
                    : "r"(taddr));
                asm volatile("tcgen05.wait::ld.sync.aligned;" ::: "memory");

                float v[32];
#pragma unroll
                for (int cc = 0; cc < 32; cc++) {
                    float a = __uint_as_float(r[cc]);
                    int lc = ch * 32 + cc;
                    if (lc >= pstart && lc < pstart + V_TXT) pos += a;
                    float e = __expf(fmaf(a, SCALE_F, -MSHIFT_F));
                    v[cc] = e;
                    rowacc += e;
                }
#pragma unroll
                for (int off = 16; off >= 1; off >>= 1) {
#pragma unroll
                    for (int cc = 0; cc < 16; cc++) {
                        if (cc < off) {
                            float sent = (lane & off) ? v[cc] : v[cc + off];
                            float rcv = __shfl_xor_sync(0xffffffffu, sent, off);
                            float keep = (lane & off) ? v[cc + off] : v[cc];
                            v[cc] = keep + rcv;
                        }
                    }
                }
                atomicAdd(&g_colsum[colBase + half * 256 + ch * 32 + lane], v[0]);
            }
            atomicAdd(&g_rowsum[row], rowacc);
            if (pos != 0.0f) atomicAdd(&g_possum, pos);

            asm volatile("tcgen05.fence::before_thread_sync;" ::: "memory");
            asm volatile("bar.sync 1, 256;" ::: "memory");
            if (tid == 0) mbar_arrive_rank0(sb + SM_EPI);

            // A reload if the next tile starts a new band (all MMAs reading the
            // old A completed: this tile's last DONE was awaited above).
            if (tt + 1 < tend) {
                int nb = (tt + 1) / NTILE_C;
                if (nb != prevband) {
                    prevband = nb;
                    load_A_band(sb, nb, (int)rank, tid);
                }
            }
        }
    } else if (tid == 256) {
        // ------------- issuer: A/B relays + MMA + DONE ----------------------
        int prevband = -1, acnt = 0, it = 0;
#pragma unroll 1
        for (int tt = tstart; tt < tend; tt++, it++) {
            const int band = tt / NTILE_C;
            if (band != prevband) {
                prevband = band;
                mbar_wait(sb + SM_AFULL, (uint32_t)acnt & 1u);
                asm volatile("fence.proxy.async.shared::cta;" ::: "memory");
                mbar_arrive_rank0(sb + SM_ABOTH);
                if (rank == 0)
                    mbar_wait_cluster(sb + SM_ABOTH, (uint32_t)acnt & 1u);
                acnt++;
            }
#pragma unroll 1
            for (int c = 0; c < 8; c++) {
                const int j = it * 8 + c;
                const int s = j % NSTAGE;
                const uint32_t ph = (uint32_t)(j / NSTAGE) & 1u;
                mbar_wait(sb + SM_FLOCAL(s), ph);
                asm volatile("fence.proxy.async.shared::cta;" ::: "memory");
                mbar_arrive_rank0(sb + SM_FULL(s));
                if (rank == 0) {
                    mbar_wait_cluster(sb + SM_FULL(s), ph);
                    if (c == 0 && it > 0)
                        mbar_wait_cluster(sb + SM_EPI, (uint32_t)(it - 1) & 1u);
                    const uint64_t ad = make_desc_sw128(sb + SM_A + (uint32_t)c * 16384u);
                    const uint64_t bd = make_desc_sw128(sb + SM_B + (uint32_t)s * 32768u);
#pragma unroll
                    for (int nh = 0; nh < 2; nh++)
#pragma unroll
                        for (int kk = 0; kk < 4; kk++)
                            mma_f16_ss_cg2(tmem + nh * 256,
                                           ad + kk * 2,
                                           bd + nh * 1024 + kk * 2,
                                           MMA_IDESC_CG2,
                                           (uint32_t)((c > 0) || (kk > 0)));
                    commit_mc(sb + SM_DONE(s));
                }
            }
        }
    }
    // (threads 257-287 fall through)

    __syncthreads();   // all 288
    if (w == 0) {
        asm volatile("tcgen05.dealloc.cta_group::2.sync.aligned.b32 %0, %1;"
                     ::"r"(tmem), "r"(512u));
    }
    asm volatile("barrier.cluster.arrive.aligned;" ::: "memory");
    asm volatile("barrier.cluster.wait.aligned;" ::: "memory");
#endif  // HAS_TCGEN05
}

// ================= PATH B: HMMA mma.sync fallback (plain sm_103) =============
__device__ __forceinline__ void mma16816(float* c, const uint32_t* a, const uint32_t* b) {
    asm volatile(
        "mma.sync.aligned.m16n8k16.row.col.f32.bf16.bf16.f32 "
        "{%0,%1,%2,%3}, {%4,%5,%6,%7}, {%8,%9}, {%0,%1,%2,%3};\n"
        : "+f"(c[0]), "+f"(c[1]), "+f"(c[2]), "+f"(c[3])
        : "r"(a[0]), "r"(a[1]), "r"(a[2]), "r"(a[3]), "r"(b[0]), "r"(b[1]));
}
__device__ __forceinline__ void cpa16(void* smem_dst, const void* gsrc) {
    uint32_t s = (uint32_t)__cvta_generic_to_shared(smem_dst);
    asm volatile("cp.async.ca.shared.global [%0], [%1], 16;\n" ::"r"(s), "l"(gsrc));
}
#define LDH 24
#define STAGE_H (128 * LDH)

__global__ void __launch_bounds__(256, 2) gemm_hmma_kernel() {
#if !HAS_TCGEN05
    __shared__ __nv_bfloat16 As[2 * STAGE_H];
    __shared__ __nv_bfloat16 Bs[2 * STAGE_H];

    const int tid = threadIdx.x;
    const int lane = tid & 31;
    const int warp = tid >> 5;
    const int g = lane >> 2;
    const int t = lane & 3;
    const int warpM = warp >> 2;
    const int warpN = warp & 3;
    const int rowBase = blockIdx.y * 128;
    const int colBase = blockIdx.x * 128;

    const int ldRow = tid >> 1;
    const int ldHalf = (tid & 1) * 8;
    const __nv_bfloat16* gA = g_imgb + (size_t)(rowBase + ldRow) * D_DIM + ldHalf;
    const __nv_bfloat16* gB = g_txtb + (size_t)(colBase + ldRow) * D_DIM + ldHalf;
    __nv_bfloat16* sA = &As[ldRow * LDH + ldHalf];
    __nv_bfloat16* sB = &Bs[ldRow * LDH + ldHalf];

    float acc[4][4][4];
#pragma unroll
    for (int mi = 0; mi < 4; mi++)
#pragma unroll
        for (int ni = 0; ni < 4; ni++)
#pragma unroll
            for (int r = 0; r < 4; r++) acc[mi][ni][r] = 0.0f;

    cpa16(sA, gA);
    cpa16(sB, gB);
    asm volatile("cp.async.commit_group;\n" ::: "memory");

    const int NSTEP = D_DIM / 16;
#pragma unroll 1
    for (int kc = 0; kc < NSTEP; kc++) {
        if (kc + 1 < NSTEP) {
            int st = (kc + 1) & 1;
            int k0 = (kc + 1) * 16;
            cpa16(sA + st * STAGE_H, gA + k0);
            cpa16(sB + st * STAGE_H, gB + k0);
            asm volatile("cp.async.commit_group;\n" ::: "memory");
            asm volatile("cp.async.wait_group 1;\n" ::: "memory");
        } else {
            asm volatile("cp.async.wait_group 0;\n" ::: "memory");
        }
        __syncthreads();

        const int buf = kc & 1;
        const uint32_t* A32 = reinterpret_cast<const uint32_t*>(As + buf * STAGE_H);
        const uint32_t* B32 = reinterpret_cast<const uint32_t*>(Bs + buf * STAGE_H);

        uint32_t a[4][4], b[4][2];
#pragma unroll
        for (int mi = 0; mi < 4; mi++) {
            int r0 = warpM * 64 + mi * 16 + g;
            a[mi][0] = A32[r0 * (LDH / 2) + t];
            a[mi][1] = A32[(r0 + 8) * (LDH / 2) + t];
            a[mi][2] = A32[r0 * (LDH / 2) + t + 4];
            a[mi][3] = A32[(r0 + 8) * (LDH / 2) + t + 4];
        }
#pragma unroll
        for (int ni = 0; ni < 4; ni++) {
            int c0 = warpN * 32 + ni * 8 + g;
            b[ni][0] = B32[c0 * (LDH / 2) + t];
            b[ni][1] = B32[c0 * (LDH / 2) + t + 4];
        }
#pragma unroll
        for (int mi = 0; mi < 4; mi++)
#pragma unroll
            for (int ni = 0; ni < 4; ni++) mma16816(acc[mi][ni], a[mi], b[ni]);

        __syncthreads();
    }

    float rp[4][2], cp[4][2];
#pragma unroll
    for (int i = 0; i < 4; i++) { rp[i][0] = rp[i][1] = cp[i][0] = cp[i][1] = 0.0f; }
    float pos = 0.0f;

#pragma unroll
    for (int mi = 0; mi < 4; mi++) {
        const int r0 = rowBase + warpM * 64 + mi * 16 + g;
        const int r1 = r0 + 8;
#pragma unroll
        for (int ni = 0; ni < 4; ni++) {
            const int c0 = colBase + warpN * 32 + ni * 8 + 2 * t;
            const int c1 = c0 + 1;
            float e00 = __expf(fmaf(acc[mi][ni][0], SCALE_F, -MSHIFT_F));
            float e01 = __expf(fmaf(acc[mi][ni][1], SCALE_F, -MSHIFT_F));
            float e10 = __expf(fmaf(acc[mi][ni][2], SCALE_F, -MSHIFT_F));
            float e11 = __expf(fmaf(acc[mi][ni][3], SCALE_F, -MSHIFT_F));
            rp[mi][0] += e00 + e01;
            rp[mi][1] += e10 + e11;
            cp[ni][0] += e00 + e10;
            cp[ni][1] += e01 + e11;
            int p0 = r0 * V_TXT;
            int p1 = r1 * V_TXT;
            if (c0 >= p0 && c0 < p0 + V_TXT) pos += acc[mi][ni][0];
            if (c1 >= p0 && c1 < p0 + V_TXT) pos += acc[mi][ni][1];
            if (c0 >= p1 && c0 < p1 + V_TXT) pos += acc[mi][ni][2];
            if (c1 >= p1 && c1 < p1 + V_TXT) pos += acc[mi][ni][3];
        }
    }

#pragma unroll
    for (int mi = 0; mi < 4; mi++)
#pragma unroll
        for (int rr = 0; rr < 2; rr++) {
            float v = rp[mi][rr];
            v += __shfl_xor_sync(0xffffffffu, v, 1);
            v += __shfl_xor_sync(0xffffffffu, v, 2);
            if (t == 0)
                atomicAdd(&g_rowsum[rowBase + warpM * 64 + mi * 16 + g + rr * 8], v);
        }
#pragma unroll
    for (int ni = 0; ni < 4; ni++)
#pragma unroll
        for (int cc = 0; cc < 2; cc++) {
            float v = cp[ni][cc];
            v += __shfl_xor_sync(0xffffffffu, v, 4);
            v += __shfl_xor_sync(0xffffffffu, v, 8);
            v += __shfl_xor_sync(0xffffffffu, v, 16);
            if (g == 0)
                atomicAdd(&g_colsum[colBase + warpN * 32 + ni * 8 + 2 * t + cc], v);
        }
    if (pos != 0.0f) atomicAdd(&g_possum, pos);
#endif  // !HAS_TCGEN05
}

// ---------------- parallel log reduction + fused writer ----------------
#define RED_BLOCKS 128
__global__ void reduce_kernel(float* out, int out_size) {
    float s = 0.0f;
    for (int i = blockIdx.x * blockDim.x + threadIdx.x; i < B_IMG;
         i += gridDim.x * blockDim.x)
        s += logf(g_rowsum[i]) * (1.0f / B_IMG);
    for (int j = blockIdx.x * blockDim.x + threadIdx.x; j < N_TXT;
         j += gridDim.x * blockDim.x)
        s += logf(g_colsum[j]) * (1.0f / N_TXT);
#pragma unroll
    for (int off = 16; off >= 1; off >>= 1) s += __shfl_xor_sync(0xffffffffu, s, off);
    __shared__ float sh[8];
    int w = threadIdx.x >> 5, lane = threadIdx.x & 31;
    if (lane == 0) sh[w] = s;
    __syncthreads();
    if (threadIdx.x == 0) {
        float b = 0.0f;
        for (int k = 0; k < 8; k++) b += sh[k];
        atomicAdd(&g_logsum, b);
        __threadfence();
        unsigned int done = atomicAdd(&g_count, 1u);
        if (done == RED_BLOCKS - 1) {
            float loss = 0.5f * (g_logsum + 2.0f * MSHIFT_F)
                         - SCALE_F * g_possum / (float)N_TXT;
            for (int k = 0; k < out_size; k++) out[k] = loss;
        }
    }
}

// ---------------- launch ----------------
extern "C" void kernel_launch(void* const* d_in, const int* in_sizes, int n_in,
                              void* d_out, int out_size) {
    const float* img = (const float*)d_in[0];
    const float* txt = (const float*)d_in[1];
    (void)in_sizes; (void)n_in;

    static int use_tc = -1;
    if (use_tc < 0) {
        cudaFuncAttributes a{};
        cudaFuncGetAttributes(&a, gemm_tc_kernel);
        use_tc = (a.numRegs > 40) ? 1 : 0;
        if (use_tc)
            cudaFuncSetAttribute(gemm_tc_kernel,
                                 cudaFuncAttributeMaxDynamicSharedMemorySize, SM_TOTAL);
    }

    convert_kernel<<<2048, 256>>>(img, txt);
    if (use_tc) {
        gemm_tc_kernel<<<2 * NCLUSTERS, 288, SM_TOTAL>>>();   // 148 CTAs, persistent
    } else {
        dim3 grid_hm(N_TXT / 128, B_IMG / 128);
        gemm_hmma_kernel<<<grid_hm, 256>>>();
    }
    reduce_kernel<<<RED_BLOCKS, 256>>>((float*)d_out, out_size);
}

// round 17
// speedup vs baseline: 1.4669x; 1.2210x over previous
#include <cuda_runtime.h>
#include <cuda_bf16.h>
#include <cuda_fp8.h>
#include <cstdint>

// Problem constants
#define B_IMG 4096
#define V_TXT 5
#define D_DIM 512
#define N_TXT (B_IMG * V_TXT)         // 20480
#define SCALE_F 14.285714285714286f   // 1/0.07
#define MSHIFT_F 14.285714285714286f
#define QSCALE 64.0f                  // fp8 pre-quantization scale
#define SCALE_EPI (SCALE_F / 4096.0f) // logit = rawacc * SCALE/(QSCALE^2)

// Arch-specific feature detection (tcgen05 requires an sm_103a/f device pass)
#if defined(__CUDA_ARCH_FEAT_SM103_ALL) || defined(__CUDA_ARCH_SPECIFIC__) || defined(__CUDA_ARCH_FAMILY_SPECIFIC__)
#define HAS_TCGEN05 1
#else
#define HAS_TCGEN05 0
#endif

// ---------------- device scratch ----------------
__device__ uint8_t g_imgf8[(size_t)B_IMG * D_DIM];   // e4m3, tc path
__device__ uint8_t g_txtf8[(size_t)N_TXT * D_DIM];
__device__ __nv_bfloat16 g_imgb[(size_t)B_IMG * D_DIM];  // bf16, fallback path
__device__ __nv_bfloat16 g_txtb[(size_t)N_TXT * D_DIM];
__device__ float g_rowsum[B_IMG];
__device__ float g_colsum[N_TXT];
__device__ float g_possum;            // RAW accumulator-space positive sum
__device__ float g_logsum;
__device__ unsigned int g_count;

// ---------------- convert + init (fused) -------------------------------------
__global__ void convert_kernel(const float* __restrict__ img,
                               const float* __restrict__ txt) {
    const int gid = blockIdx.x * blockDim.x + threadIdx.x;
    if (gid < B_IMG) g_rowsum[gid] = 0.0f;
    if (gid < N_TXT) g_colsum[gid] = 0.0f;
    if (gid == 0) { g_possum = 0.0f; g_logsum = 0.0f; g_count = 0u; }

    const int IMG8 = B_IMG * D_DIM / 8;
    const int TOT8 = IMG8 + N_TXT * D_DIM / 8;
    for (int i = gid; i < TOT8; i += gridDim.x * blockDim.x) {
        const float4* src;
        int isimg = (i < IMG8);
        int j = isimg ? i : i - IMG8;
        src = reinterpret_cast<const float4*>(isimg ? img : txt) + 2 * (size_t)j;
        float4 v0 = src[0], v1 = src[1];
#if HAS_TCGEN05
        __nv_fp8x2_storage_t p0 = __nv_cvt_float2_to_fp8x2(
            make_float2(v0.x * QSCALE, v0.y * QSCALE), __NV_SATFINITE, __NV_E4M3);
        __nv_fp8x2_storage_t p1 = __nv_cvt_float2_to_fp8x2(
            make_float2(v0.z * QSCALE, v0.w * QSCALE), __NV_SATFINITE, __NV_E4M3);
        __nv_fp8x2_storage_t p2 = __nv_cvt_float2_to_fp8x2(
            make_float2(v1.x * QSCALE, v1.y * QSCALE), __NV_SATFINITE, __NV_E4M3);
        __nv_fp8x2_storage_t p3 = __nv_cvt_float2_to_fp8x2(
            make_float2(v1.z * QSCALE, v1.w * QSCALE), __NV_SATFINITE, __NV_E4M3);
        uint2 o;
        o.x = (uint32_t)p0 | ((uint32_t)p1 << 16);
        o.y = (uint32_t)p2 | ((uint32_t)p3 << 16);
        uint2* dst = reinterpret_cast<uint2*>(isimg ? g_imgf8 : g_txtf8) + j;
        *dst = o;
#else
        union { __nv_bfloat162 h[4]; uint4 u; } o;
        o.h[0] = __floats2bfloat162_rn(v0.x, v0.y);
        o.h[1] = __floats2bfloat162_rn(v0.z, v0.w);
        o.h[2] = __floats2bfloat162_rn(v1.x, v1.y);
        o.h[3] = __floats2bfloat162_rn(v1.z, v1.w);
        uint4* dst = reinterpret_cast<uint4*>(isimg ? g_imgb : g_txtb) + j;
        *dst = o.u;
#endif
    }
}

// ===== PATH A: persistent tcgen05 cg2 FP8 (R16 skeleton) =====================
// 74 clusters x 2 CTAs, 288 threads: warps 0-7 load + epilogue, tid256 issuer.
// N=512 tiles, band-major ranges. A e4m3 (128 rows x 512 = 64KB/CTA) resident
// per band; B streamed via 4-stage 32KB ring. 4 K-chunks of 128 fp8 elements
// per tile; per chunk 2 halves x 4 K-steps of kind::f8f6f4 MMA (K=32 each).
// Byte geometry identical to the proven bf16 kernel.
#define NCLUSTERS 74
#define NTILE_C   40
#define NTILES    640
#define NCHNK     4                    // K-chunks per tile (512 / 128)
#define NSTAGE    4

#define SM_TMEMPTR 0u
#define SM_AFULL   8u                            // cnt=256 (A cp.async)
#define SM_ABOTH   16u                           // cnt=2
#define SM_FLOCAL(s) (24u + 8u*(uint32_t)(s))    // cnt=256 (B cp.async)
#define SM_FULL(s)   (56u + 8u*(uint32_t)(s))    // cnt=2
#define SM_DONE(s)   (88u + 8u*(uint32_t)(s))    // cnt=1 (multicast commit)
#define SM_EPI       120u                         // cnt=2
#define SM_A       1024u                          // 4 x 16KB = 64KB persistent
#define SM_B       66560u                         // 4 x 32KB ring
#define SM_TOTAL   197632u

// idesc kind::f8f6f4: dtype f32 (bit4), atype=btype=E4M3 (0), N=256, M=256
#define MMA_IDESC_F8 ((1u<<4)|((256u/8u)<<17)|((256u/16u)<<24))
#define SWZ(x) ((x) ^ (((x) >> 3) & 0x70))

__device__ __forceinline__ uint32_t smem_u32(const void* p) {
    return (uint32_t)__cvta_generic_to_shared(p);
}
__device__ __forceinline__ void cp16(uint32_t saddr, const void* g) {
    asm volatile("cp.async.cg.shared.global [%0], [%1], 16;\n" ::"r"(saddr), "l"(g));
}
__device__ __forceinline__ void mbar_init(uint32_t a, uint32_t cnt) {
    asm volatile("mbarrier.init.shared.b64 [%0], %1;" ::"r"(a), "r"(cnt) : "memory");
}
__device__ __forceinline__ void mbar_wait(uint32_t a, uint32_t parity) {
    uint32_t done;
    asm volatile(
        "{\n\t.reg .pred p;\n\t"
        "mbarrier.try_wait.parity.acquire.cta.shared::cta.b64 p, [%1], %2;\n\t"
        "selp.b32 %0, 1, 0, p;\n\t}"
        : "=r"(done) : "r"(a), "r"(parity) : "memory");
    if (!done) {
        asm volatile(
            "{\n\t.reg .pred P1;\n\t"
            "W_%=:\n\t"
            "mbarrier.try_wait.parity.acquire.cta.shared::cta.b64 P1, [%0], %1, 0x989680;\n\t"
            "@P1 bra.uni D_%=;\n\t"
            "bra.uni W_%=;\n\t"
            "D_%=:\n\t}"
            :: "r"(a), "r"(parity) : "memory");
    }
}
__device__ __forceinline__ void mbar_wait_cluster(uint32_t a, uint32_t parity) {
    asm volatile(
        "{\n\t.reg .pred P1;\n\t"
        "W_%=:\n\t"
        "mbarrier.try_wait.parity.acquire.cluster.shared::cta.b64 P1, [%0], %1, 0x989680;\n\t"
        "@P1 bra.uni D_%=;\n\t"
        "bra.uni W_%=;\n\t"
        "D_%=:\n\t}"
        :: "r"(a), "r"(parity) : "memory");
}
__device__ __forceinline__ void mbar_arrive_rank0(uint32_t local_addr) {
    asm volatile(
        "{\n\t.reg .b32 r;\n\t"
        "mapa.shared::cluster.u32 r, %0, 0;\n\t"
        "mbarrier.arrive.shared::cluster.b64 _, [r];\n\t}"
        :: "r"(local_addr) : "memory");
}

#if HAS_TCGEN05
__device__ __forceinline__ uint64_t make_desc_sw128(uint32_t addr) {
    const uint64_t base = (uint64_t(2) << 61) | (uint64_t(1) << 46) |
                          (uint64_t(64) << 32) | (uint64_t(1) << 16);
    return base | ((uint64_t)(addr >> 4) & 0x3FFF);
}
__device__ __forceinline__ void mma_f8_ss_cg2(uint32_t d, uint64_t ad, uint64_t bd,
                                              uint32_t idesc, uint32_t en) {
    asm volatile(
        "{\n\t.reg .pred p;\n\t"
        "setp.ne.u32 p, %4, 0;\n\t"
        "tcgen05.mma.cta_group::2.kind::f8f6f4 [%0], %1, %2, %3, "
        "{%5,%5,%5,%5,%5,%5,%5,%5}, p;\n\t}"
        :: "r"(d), "l"(ad), "l"(bd), "r"(idesc), "r"(en), "r"(0u) : "memory");
}
__device__ __forceinline__ void commit_mc(uint32_t addr) {
    asm volatile(
        "tcgen05.commit.cta_group::2.mbarrier::arrive::one"
        ".shared::cluster.multicast::cluster.b64 [%0], %1;"
        ::"r"(addr), "h"((uint16_t)0x3) : "memory");
}
// Full A band (this CTA's 128 rows x 512 fp8 = 64KB) into smem; arrive AFULL.
__device__ __forceinline__ void load_A_band(uint32_t sb, int band, int rank, int tid) {
    const int rowBase = band * 256 + rank * 128;
#pragma unroll
    for (int i = 0; i < 16; i++) {          // 4096 x16B
        int idx = tid + i * 256;
        int c = idx >> 10;                  // chunk 0..3 (K block of 128)
        int rr = (idx & 1023) >> 3, seg = idx & 7;
        cp16(sb + SM_A + (uint32_t)c * 16384u + SWZ((uint32_t)(rr * 128 + seg * 16)),
             g_imgf8 + (size_t)(rowBase + rr) * D_DIM + c * 128 + seg * 16);
    }
    asm volatile("cp.async.mbarrier.arrive.noinc.shared::cta.b64 [%0];"
                 ::"r"(sb + SM_AFULL) : "memory");
}
// B chunk (this CTA's 256 local rows, K block c of 128) into stage s.
__device__ __forceinline__ void load_B(uint32_t sb, int s, int tt, int c,
                                       int rank, int tid) {
    const int colBase = (tt % NTILE_C) * 512;
    const uint32_t stg = sb + SM_B + (uint32_t)s * 32768u;
#pragma unroll
    for (int i = 0; i < 8; i++) {           // 2048 x16B
        int idx = tid + i * 256;
        int lr = idx >> 3, seg = idx & 7;
        int grow = colBase + ((lr >> 7) << 8) + rank * 128 + (lr & 127);
        cp16(stg + SWZ((uint32_t)(lr * 128 + seg * 16)),
             g_txtf8 + (size_t)grow * D_DIM + c * 128 + seg * 16);
    }
    asm volatile("cp.async.mbarrier.arrive.noinc.shared::cta.b64 [%0];"
                 ::"r"(sb + SM_FLOCAL(s)) : "memory");
}
#endif  // HAS_TCGEN05

__global__ void __launch_bounds__(288, 1) __cluster_dims__(2, 1, 1)
gemm_tc_kernel() {
#if HAS_TCGEN05
    extern __shared__ char smem[];
    const uint32_t sb = smem_u32(smem);
    const int tid = threadIdx.x;
    const int w = tid >> 5, lane = tid & 31;
    uint32_t rank;
    asm("mov.u32 %0, %%cluster_ctarank;" : "=r"(rank));
    const int cid = blockIdx.x >> 1;
    const int tstart = (cid * NTILES) / NCLUSTERS;
    const int tend   = ((cid + 1) * NTILES) / NCLUSTERS;

    if (w == 0) {
        asm volatile("tcgen05.alloc.cta_group::2.sync.aligned.shared::cta.b32 [%0], %1;"
                     ::"r"(sb + SM_TMEMPTR), "r"(512u) : "memory");
        asm volatile("tcgen05.relinquish_alloc_permit.cta_group::2.sync.aligned;");
    }
    if (tid == 0) {
        mbar_init(sb + SM_AFULL, 256);
        mbar_init(sb + SM_ABOTH, 2);
#pragma unroll
        for (int s = 0; s < NSTAGE; s++) {
            mbar_init(sb + SM_FLOCAL(s), 256);
            mbar_init(sb + SM_FULL(s), 2);
            mbar_init(sb + SM_DONE(s), 1);
        }
        mbar_init(sb + SM_EPI, 2);
    }
    __syncthreads();
    asm volatile("barrier.cluster.arrive.aligned;" ::: "memory");
    asm volatile("barrier.cluster.wait.aligned;" ::: "memory");

    uint32_t tmem;
    asm volatile("ld.shared.b32 %0, [%1];" : "=r"(tmem) : "r"(sb + SM_TMEMPTR));

    if (tid < 256) {
        // ------------- load warps 0-7 + per-tile epilogue -------------------
        int prevband = tstart / NTILE_C;
        load_A_band(sb, prevband, (int)rank, tid);
        load_B(sb, 0, tstart, 0, (int)rank, tid);

        int kl = 0;
#pragma unroll 1
        for (int tt = tstart; tt < tend; tt++) {
            const int rowBase = (tt / NTILE_C) * 256 + (int)rank * 128;
            const int colBase = (tt % NTILE_C) * 512;

#pragma unroll 1
            for (int c = 0; c < NCHNK; c++, kl++) {
                // stage (kl+1)%4 previous occupant = chunk kl-3; wait its MMA
                if (kl >= 3)
                    mbar_wait(sb + SM_DONE((kl - 3) % NSTAGE),
                              (uint32_t)((kl - 3) / NSTAGE) & 1u);
                if (c < NCHNK - 1)
                    load_B(sb, (kl + 1) % NSTAGE, tt, c + 1, (int)rank, tid);
                else if (tt + 1 < tend)
                    load_B(sb, (kl + 1) % NSTAGE, tt + 1, 0, (int)rank, tid);
            }

            // ---- epilogue: wait this tile's last chunk MMA ----
            mbar_wait(sb + SM_DONE((kl - 1) % NSTAGE),
                      (uint32_t)((kl - 1) / NSTAGE) & 1u);
            asm volatile("tcgen05.fence::after_thread_sync;" ::: "memory");

            const int half = w >> 2, sp = w & 3;
            const int row = rowBase + sp * 32 + lane;
            float rowacc = 0.0f, pos = 0.0f;
            const int pstart = row * V_TXT - colBase - half * 256;

#pragma unroll 1
            for (int ch = 0; ch < 8; ch++) {
                uint32_t r[32];
                uint32_t taddr = tmem + half * 256 + ch * 32;
                asm volatile(
                    "tcgen05.ld.sync.aligned.32x32b.x32.b32 "
                    "{%0,%1,%2,%3,%4,%5,%6,%7,%8,%9,%10,%11,%12,%13,%14,%15,"
                    "%16,%17,%18,%19,%20,%21,%22,%23,%24,%25,%26,%27,%28,%29,%30,%31}, [%32];"
                    : "=r"(r[0]), "=r"(r[1]), "=r"(r[2]), "=r"(r[3]), "=r"(r[4]),
                      "=r"(r[5]), "=r"(r[6]), "=r"(r[7]), "=r"(r[8]), "=r"(r[9]),
                      "=r"(r[10]), "=r"(r[11]), "=r"(r[12]), "=r"(r[13]), "=r"(r[14]),
                      "=r"(r[15]), "=r"(r[16]), "=r"(r[17]), "=r"(r[18]), "=r"(r[19]),
                      "=r"(r[20]), "=r"(r[21]), "=r"(r[22]), "=r"(r[23]), "=r"(r[24]),
                      "=r"(r[25]), "=r"(r[26]), "=r"(r[27]), "=r"(r[28]), "=r"(r[29]),
                      "=r"(r[30]), "=r"(r[31])
                    : "r"(taddr));
                asm volatile("tcgen05.wait::ld.sync.aligned;" ::: "memory");

                float v[32];
#pragma unroll
                for (int cc = 0; cc < 32; cc++) {
                    float a = __uint_as_float(r[cc]);
                    int lc = ch * 32 + cc;
                    if (lc >= pstart && lc < pstart + V_TXT) pos += a;  // raw acc
                    float e = __expf(fmaf(a, SCALE_EPI, -MSHIFT_F));
                    v[cc] = e;
                    rowacc += e;
                }
#pragma unroll
                for (int off = 16; off >= 1; off >>= 1) {
#pragma unroll
                    for (int cc = 0; cc < 16; cc++) {
                        if (cc < off) {
                            float sent = (lane & off) ? v[cc] : v[cc + off];
                            float rcv = __shfl_xor_sync(0xffffffffu, sent, off);
                            float keep = (lane & off) ? v[cc + off] : v[cc];
                            v[cc] = keep + rcv;
                        }
                    }
                }
                atomicAdd(&g_colsum[colBase + half * 256 + ch * 32 + lane], v[0]);
            }
            atomicAdd(&g_rowsum[row], rowacc);
            if (pos != 0.0f) atomicAdd(&g_possum, pos);

            asm volatile("tcgen05.fence::before_thread_sync;" ::: "memory");
            asm volatile("bar.sync 1, 256;" ::: "memory");
            if (tid == 0) mbar_arrive_rank0(sb + SM_EPI);

            if (tt + 1 < tend) {
                int nb = (tt + 1) / NTILE_C;
                if (nb != prevband) {
                    prevband = nb;
                    load_A_band(sb, nb, (int)rank, tid);
                }
            }
        }
    } else if (tid == 256) {
        // ------------- issuer: A/B relays + MMA + DONE ----------------------
        int prevband = -1, acnt = 0, it = 0;
#pragma unroll 1
        for (int tt = tstart; tt < tend; tt++, it++) {
            const int band = tt / NTILE_C;
            if (band != prevband) {
                prevband = band;
                mbar_wait(sb + SM_AFULL, (uint32_t)acnt & 1u);
                asm volatile("fence.proxy.async.shared::cta;" ::: "memory");
                mbar_arrive_rank0(sb + SM_ABOTH);
                if (rank == 0)
                    mbar_wait_cluster(sb + SM_ABOTH, (uint32_t)acnt & 1u);
                acnt++;
            }
#pragma unroll 1
            for (int c = 0; c < NCHNK; c++) {
                const int j = it * NCHNK + c;
                const int s = j % NSTAGE;
                const uint32_t ph = (uint32_t)(j / NSTAGE) & 1u;
                mbar_wait(sb + SM_FLOCAL(s), ph);
                asm volatile("fence.proxy.async.shared::cta;" ::: "memory");
                mbar_arrive_rank0(sb + SM_FULL(s));
                if (rank == 0) {
                    mbar_wait_cluster(sb + SM_FULL(s), ph);
                    if (c == 0 && it > 0)
                        mbar_wait_cluster(sb + SM_EPI, (uint32_t)(it - 1) & 1u);
                    const uint64_t ad = make_desc_sw128(sb + SM_A + (uint32_t)c * 16384u);
                    const uint64_t bd = make_desc_sw128(sb + SM_B + (uint32_t)s * 32768u);
#pragma unroll
                    for (int nh = 0; nh < 2; nh++)
#pragma unroll
                        for (int kk = 0; kk < 4; kk++)
                            mma_f8_ss_cg2(tmem + nh * 256,
                                          ad + kk * 2,
                                          bd + nh * 1024 + kk * 2,
                                          MMA_IDESC_F8,
                                          (uint32_t)((c > 0) || (kk > 0)));
                    commit_mc(sb + SM_DONE(s));
                }
            }
        }
    }

    __syncthreads();   // all 288
    if (w == 0) {
        asm volatile("tcgen05.dealloc.cta_group::2.sync.aligned.b32 %0, %1;"
                     ::"r"(tmem), "r"(512u));
    }
    asm volatile("barrier.cluster.arrive.aligned;" ::: "memory");
    asm volatile("barrier.cluster.wait.aligned;" ::: "memory");
#endif  // HAS_TCGEN05
}

// ================= PATH B: HMMA mma.sync fallback (plain sm_103) =============
__device__ __forceinline__ void mma16816(float* c, const uint32_t* a, const uint32_t* b) {
    asm volatile(
        "mma.sync.aligned.m16n8k16.row.col.f32.bf16.bf16.f32 "
        "{%0,%1,%2,%3}, {%4,%5,%6,%7}, {%8,%9}, {%0,%1,%2,%3};\n"
        : "+f"(c[0]), "+f"(c[1]), "+f"(c[2]), "+f"(c[3])
        : "r"(a[0]), "r"(a[1]), "r"(a[2]), "r"(a[3]), "r"(b[0]), "r"(b[1]));
}
__device__ __forceinline__ void cpa16(void* smem_dst, const void* gsrc) {
    uint32_t s = (uint32_t)__cvta_generic_to_shared(smem_dst);
    asm volatile("cp.async.ca.shared.global [%0], [%1], 16;\n" ::"r"(s), "l"(gsrc));
}
#define LDH 24
#define STAGE_H (128 * LDH)

__global__ void __launch_bounds__(256, 2) gemm_hmma_kernel() {
#if !HAS_TCGEN05
    __shared__ __nv_bfloat16 As[2 * STAGE_H];
    __shared__ __nv_bfloat16 Bs[2 * STAGE_H];

    const int tid = threadIdx.x;
    const int lane = tid & 31;
    const int warp = tid >> 5;
    const int g = lane >> 2;
    const int t = lane & 3;
    const int warpM = warp >> 2;
    const int warpN = warp & 3;
    const int rowBase = blockIdx.y * 128;
    const int colBase = blockIdx.x * 128;

    const int ldRow = tid >> 1;
    const int ldHalf = (tid & 1) * 8;
    const __nv_bfloat16* gA = g_imgb + (size_t)(rowBase + ldRow) * D_DIM + ldHalf;
    const __nv_bfloat16* gB = g_txtb + (size_t)(colBase + ldRow) * D_DIM + ldHalf;
    __nv_bfloat16* sA = &As[ldRow * LDH + ldHalf];
    __nv_bfloat16* sB = &Bs[ldRow * LDH + ldHalf];

    float acc[4][4][4];
#pragma unroll
    for (int mi = 0; mi < 4; mi++)
#pragma unroll
        for (int ni = 0; ni < 4; ni++)
#pragma unroll
            for (int r = 0; r < 4; r++) acc[mi][ni][r] = 0.0f;

    cpa16(sA, gA);
    cpa16(sB, gB);
    asm volatile("cp.async.commit_group;\n" ::: "memory");

    const int NSTEP = D_DIM / 16;
#pragma unroll 1
    for (int kc = 0; kc < NSTEP; kc++) {
        if (kc + 1 < NSTEP) {
            int st = (kc + 1) & 1;
            int k0 = (kc + 1) * 16;
            cpa16(sA + st * STAGE_H, gA + k0);
            cpa16(sB + st * STAGE_H, gB + k0);
            asm volatile("cp.async.commit_group;\n" ::: "memory");
            asm volatile("cp.async.wait_group 1;\n" ::: "memory");
        } else {
            asm volatile("cp.async.wait_group 0;\n" ::: "memory");
        }
        __syncthreads();

        const int buf = kc & 1;
        const uint32_t* A32 = reinterpret_cast<const uint32_t*>(As + buf * STAGE_H);
        const uint32_t* B32 = reinterpret_cast<const uint32_t*>(Bs + buf * STAGE_H);

        uint32_t a[4][4], b[4][2];
#pragma unroll
        for (int mi = 0; mi < 4; mi++) {
            int r0 = warpM * 64 + mi * 16 + g;
            a[mi][0] = A32[r0 * (LDH / 2) + t];
            a[mi][1] = A32[(r0 + 8) * (LDH / 2) + t];
            a[mi][2] = A32[r0 * (LDH / 2) + t + 4];
            a[mi][3] = A32[(r0 + 8) * (LDH / 2) + t + 4];
        }
#pragma unroll
        for (int ni = 0; ni < 4; ni++) {
            int c0 = warpN * 32 + ni * 8 + g;
            b[ni][0] = B32[c0 * (LDH / 2) + t];
            b[ni][1] = B32[c0 * (LDH / 2) + t + 4];
        }
#pragma unroll
        for (int mi = 0; mi < 4; mi++)
#pragma unroll
            for (int ni = 0; ni < 4; ni++) mma16816(acc[mi][ni], a[mi], b[ni]);

        __syncthreads();
    }

    float rp[4][2], cp[4][2];
#pragma unroll
    for (int i = 0; i < 4; i++) { rp[i][0] = rp[i][1] = cp[i][0] = cp[i][1] = 0.0f; }
    float pos = 0.0f;

#pragma unroll
    for (int mi = 0; mi < 4; mi++) {
        const int r0 = rowBase + warpM * 64 + mi * 16 + g;
        const int r1 = r0 + 8;
#pragma unroll
        for (int ni = 0; ni < 4; ni++) {
            const int c0 = colBase + warpN * 32 + ni * 8 + 2 * t;
            const int c1 = c0 + 1;
            float e00 = __expf(fmaf(acc[mi][ni][0], SCALE_F, -MSHIFT_F));
            float e01 = __expf(fmaf(acc[mi][ni][1], SCALE_F, -MSHIFT_F));
            float e10 = __expf(fmaf(acc[mi][ni][2], SCALE_F, -MSHIFT_F));
            float e11 = __expf(fmaf(acc[mi][ni][3], SCALE_F, -MSHIFT_F));
            rp[mi][0] += e00 + e01;
            rp[mi][1] += e10 + e11;
            cp[ni][0] += e00 + e10;
            cp[ni][1] += e01 + e11;
            int p0 = r0 * V_TXT;
            int p1 = r1 * V_TXT;
            if (c0 >= p0 && c0 < p0 + V_TXT) pos += acc[mi][ni][0];
            if (c1 >= p0 && c1 < p0 + V_TXT) pos += acc[mi][ni][1];
            if (c0 >= p1 && c0 < p1 + V_TXT) pos += acc[mi][ni][2];
            if (c1 >= p1 && c1 < p1 + V_TXT) pos += acc[mi][ni][3];
        }
    }

#pragma unroll
    for (int mi = 0; mi < 4; mi++)
#pragma unroll
        for (int rr = 0; rr < 2; rr++) {
            float v = rp[mi][rr];
            v += __shfl_xor_sync(0xffffffffu, v, 1);
            v += __shfl_xor_sync(0xffffffffu, v, 2);
            if (t == 0)
                atomicAdd(&g_rowsum[rowBase + warpM * 64 + mi * 16 + g + rr * 8], v);
        }
#pragma unroll
    for (int ni = 0; ni < 4; ni++)
#pragma unroll
        for (int cc = 0; cc < 2; cc++) {
            float v = cp[ni][cc];
            v += __shfl_xor_sync(0xffffffffu, v, 4);
            v += __shfl_xor_sync(0xffffffffu, v, 8);
            v += __shfl_xor_sync(0xffffffffu, v, 16);
            if (g == 0)
                atomicAdd(&g_colsum[colBase + warpN * 32 + ni * 8 + 2 * t + cc], v);
        }
    if (pos != 0.0f) atomicAdd(&g_possum, pos);
#endif  // !HAS_TCGEN05
}

// ---------------- parallel log reduction + fused writer ----------------
#define RED_BLOCKS 128
__global__ void reduce_kernel(float* out, int out_size) {
    float s = 0.0f;
    for (int i = blockIdx.x * blockDim.x + threadIdx.x; i < B_IMG;
         i += gridDim.x * blockDim.x)
        s += logf(g_rowsum[i]) * (1.0f / B_IMG);
    for (int j = blockIdx.x * blockDim.x + threadIdx.x; j < N_TXT;
         j += gridDim.x * blockDim.x)
        s += logf(g_colsum[j]) * (1.0f / N_TXT);
#pragma unroll
    for (int off = 16; off >= 1; off >>= 1) s += __shfl_xor_sync(0xffffffffu, s, off);
    __shared__ float sh[8];
    int w = threadIdx.x >> 5, lane = threadIdx.x & 31;
    if (lane == 0) sh[w] = s;
    __syncthreads();
    if (threadIdx.x == 0) {
        float b = 0.0f;
        for (int k = 0; k < 8; k++) b += sh[k];
        atomicAdd(&g_logsum, b);
        __threadfence();
        unsigned int done = atomicAdd(&g_count, 1u);
        if (done == RED_BLOCKS - 1) {
#if HAS_TCGEN05
            const float pscale = SCALE_EPI;   // raw fp8 acc -> logit
#else
            const float pscale = SCALE_F;     // raw bf16 dot -> logit
#endif
            float loss = 0.5f * (g_logsum + 2.0f * MSHIFT_F)
                         - pscale * g_possum / (float)N_TXT;
            for (int k = 0; k < out_size; k++) out[k] = loss;
        }
    }
}

// ---------------- launch ----------------
extern "C" void kernel_launch(void* const* d_in, const int* in_sizes, int n_in,
                              void* d_out, int out_size) {
    const float* img = (const float*)d_in[0];
    const float* txt = (const float*)d_in[1];
    (void)in_sizes; (void)n_in;

    static int use_tc = -1;
    if (use_tc < 0) {
        cudaFuncAttributes a{};
        cudaFuncGetAttributes(&a, gemm_tc_kernel);
        use_tc = (a.numRegs > 40) ? 1 : 0;
        if (use_tc)
            cudaFuncSetAttribute(gemm_tc_kernel,
                                 cudaFuncAttributeMaxDynamicSharedMemorySize, SM_TOTAL);
    }

    convert_kernel<<<2048, 256>>>(img, txt);
    if (use_tc) {
        gemm_tc_kernel<<<2 * NCLUSTERS, 288, SM_TOTAL>>>();   // 148 CTAs, persistent
    } else {
        dim3 grid_hm(N_TXT / 128, B_IMG / 128);
        gemm_hmma_kernel<<<grid_hm, 256>>>();
    }
    reduce_kernel<<<RED_BLOCKS, 256>>>((float*)d_out, out_size);
}